// round 2
// baseline (speedup 1.0000x reference)
#include <cuda_runtime.h>
#include <cuda_bf16.h>

// CenterLoss, B=1024, C=100000, F=128.
// loss = ( sum_b clip(||x_b - centers[labels_b]||^2, 1e-12, 1e12)
//          + (B*C - B)*1e-12 ) / B
// One-hot mask + clip => full [B,C] distmat never needed.
// Single kernel: per-block partials + "last block reduces" via atomic counter.

#define BATCH     1024
#define FEAT      128
#define NBLOCKS   128
#define WARPS_PER_BLOCK 8
// (B*C - B) * 1e-12 = 1024*99999*1e-12
#define MASK_CONST 1.02398976e-4f

__device__ float        g_partials[NBLOCKS];
__device__ unsigned int g_count = 0;   // reset to 0 by the last block each call

__global__ __launch_bounds__(WARPS_PER_BLOCK * 32)
void centerloss_fused(const float* __restrict__ x,
                      const int*   __restrict__ labels,
                      const float* __restrict__ centers,
                      float*       __restrict__ out) {
    const int warp = threadIdx.x >> 5;
    const int lane = threadIdx.x & 31;
    const int row  = blockIdx.x * WARPS_PER_BLOCK + warp;   // 0..1023

    // One warp per row; each lane handles one float4 of the 128-dim row.
    const float4* xr = reinterpret_cast<const float4*>(x + (size_t)row * FEAT);
    const int lbl = labels[row];
    const float4* cr = reinterpret_cast<const float4*>(centers + (size_t)lbl * FEAT);

    float4 a = xr[lane];
    float4 c = cr[lane];
    float dx = a.x - c.x, dy = a.y - c.y, dz = a.z - c.z, dw = a.w - c.w;
    float d = dx * dx + dy * dy + dz * dz + dw * dw;

    // warp tree reduce (fixed order -> deterministic)
    #pragma unroll
    for (int o = 16; o > 0; o >>= 1)
        d += __shfl_xor_sync(0xFFFFFFFFu, d, o);

    __shared__ float warp_sums[WARPS_PER_BLOCK];
    __shared__ bool  is_last;
    if (lane == 0)
        warp_sums[warp] = fminf(fmaxf(d, 1e-12f), 1e12f);  // per-row clip
    __syncthreads();

    if (threadIdx.x == 0) {
        float s = 0.0f;
        #pragma unroll
        for (int w = 0; w < WARPS_PER_BLOCK; w++) s += warp_sums[w];
        g_partials[blockIdx.x] = s;
        __threadfence();                         // partial visible before count bump
        unsigned int t = atomicAdd(&g_count, 1u);
        is_last = (t == NBLOCKS - 1u);
    }
    __syncthreads();

    if (!is_last) return;

    // Last block: reduce all 128 partials in fixed order (deterministic).
    __threadfence();                             // acquire: see all partials
    const int tid = threadIdx.x;
    float v = (tid < NBLOCKS) ? ((volatile float*)g_partials)[tid] : 0.0f;

    #pragma unroll
    for (int o = 16; o > 0; o >>= 1)
        v += __shfl_xor_sync(0xFFFFFFFFu, v, o);

    __shared__ float ws[WARPS_PER_BLOCK];
    if (lane == 0) ws[warp] = v;
    __syncthreads();

    if (tid == 0) {
        float total = 0.0f;
        #pragma unroll
        for (int w = 0; w < 4; w++) total += ws[w];  // partials live in warps 0..3
        out[0] = (total + MASK_CONST) / (float)BATCH;
        g_count = 0;                             // re-arm for next graph replay
    }
}

extern "C" void kernel_launch(void* const* d_in, const int* in_sizes, int n_in,
                              void* d_out, int out_size) {
    const float* x       = (const float*)d_in[0];   // [1024, 128] f32
    const int*   labels  = (const int*)  d_in[1];   // [1024] i32
    const float* centers = (const float*)d_in[2];   // [100000, 128] f32
    float* out = (float*)d_out;

    centerloss_fused<<<NBLOCKS, WARPS_PER_BLOCK * 32>>>(x, labels, centers, out);
}

// round 3
// speedup vs baseline: 1.2266x; 1.2266x over previous
#include <cuda_runtime.h>
#include <cuda_bf16.h>

// CenterLoss, B=1024, C=100000, F=128.
// loss = ( sum_b clip(||x_b - centers[labels_b]||^2, 1e-12, 1e12)
//          + (B*C - B)*1e-12 ) / B
// One-hot mask + clip => the [B,C] distmat is never materialized.
//
// Two minimal kernels (R1 structure, trimmed):
//   k1: one warp per row -> clipped row distance straight to g_row[row]
//       (no smem, no barriers, no atomics)
//   k2: single block reduces 1024 row sums in fixed order.

#define BATCH     1024
#define FEAT      128
#define NBLOCKS   128
#define WARPS_PER_BLOCK 8
// (B*C - B) * 1e-12 = 1024*99999*1e-12
#define MASK_CONST 1.02398976e-4f
#define INV_BATCH 0.0009765625f   // 1/1024, exact

__device__ float g_row[BATCH];    // per-row clipped squared distances

__global__ __launch_bounds__(WARPS_PER_BLOCK * 32)
void centerloss_rows(const float* __restrict__ x,
                     const int*   __restrict__ labels,
                     const float* __restrict__ centers) {
    const int warp = threadIdx.x >> 5;
    const int lane = threadIdx.x & 31;
    const int row  = blockIdx.x * WARPS_PER_BLOCK + warp;   // 0..1023

    // One warp per row; each lane one float4 of the 128-dim row.
    const float4* xr = reinterpret_cast<const float4*>(x + (size_t)row * FEAT);
    const int lbl = __ldg(labels + row);
    const float4* cr = reinterpret_cast<const float4*>(centers + (size_t)lbl * FEAT);

    float4 a = __ldg(xr + lane);
    float4 c = __ldg(cr + lane);
    float dx = a.x - c.x, dy = a.y - c.y, dz = a.z - c.z, dw = a.w - c.w;
    float d = fmaf(dx, dx, fmaf(dy, dy, fmaf(dz, dz, dw * dw)));

    // warp tree reduce (fixed order -> deterministic)
    #pragma unroll
    for (int o = 16; o > 0; o >>= 1)
        d += __shfl_xor_sync(0xFFFFFFFFu, d, o);

    if (lane == 0)
        g_row[row] = fminf(fmaxf(d, 1e-12f), 1e12f);   // per-row clip
}

__global__ __launch_bounds__(128)
void centerloss_finalize(float* __restrict__ out) {
    const int tid  = threadIdx.x;       // 0..127
    const int lane = tid & 31;
    const int warp = tid >> 5;

    // 128 threads x 8 floats (2 float4) = 1024 row sums
    const float4* p = reinterpret_cast<const float4*>(g_row);
    float4 a = p[tid * 2];
    float4 b = p[tid * 2 + 1];
    float v = ((a.x + a.y) + (a.z + a.w)) + ((b.x + b.y) + (b.z + b.w));

    #pragma unroll
    for (int o = 16; o > 0; o >>= 1)
        v += __shfl_xor_sync(0xFFFFFFFFu, v, o);

    __shared__ float ws[4];
    if (lane == 0) ws[warp] = v;
    __syncthreads();

    if (tid == 0) {
        float total = (ws[0] + ws[1]) + (ws[2] + ws[3]);
        out[0] = (total + MASK_CONST) * INV_BATCH;
    }
}

extern "C" void kernel_launch(void* const* d_in, const int* in_sizes, int n_in,
                              void* d_out, int out_size) {
    const float* x       = (const float*)d_in[0];   // [1024, 128] f32
    const int*   labels  = (const int*)  d_in[1];   // [1024] i32
    const float* centers = (const float*)d_in[2];   // [100000, 128] f32
    float* out = (float*)d_out;

    centerloss_rows<<<NBLOCKS, WARPS_PER_BLOCK * 32>>>(x, labels, centers);
    centerloss_finalize<<<1, 128>>>(out);
}